// round 4
// baseline (speedup 1.0000x reference)
#include <cuda_runtime.h>

#define GRIDN 192
#define VOLN (GRIDN*GRIDN*GRIDN)
#define BMW (GRIDN*GRIDN*6)
#define NBINS 80
#define MAXN 200000
#define MAXNB 32
#define PAIR_CAP 640000
#define TILE 128

// ---------------- persistent device scratch (no runtime alloc allowed) ----------------
// NOTE: g_vol needs NO per-launch clear: it is only read at cells whose g_bm bit
// is set, and bits are only set at cells k_scatter wrote in THIS launch.
__device__ int            g_vol[VOLN];                 // cell -> point index       (28.3 MB)
__device__ unsigned       g_bm[BMW];                   // occupancy bitfield, z-packed (884 KB)
__device__ float          g_K[NBINS*6400];             // 80 compacted 80x80 kernels  (2.05 MB)
__device__ int            g_rowmask[25];
__device__ int            g_rowstart[25];
__device__ int            g_bdx[NBINS], g_bdy[NBINS], g_bdz[NBINS];
__device__ int            g_counts[NBINS];
__device__ int            g_cursor[NBINS];
__device__ int            g_binstart[NBINS+1];
__device__ int            g_tilestart[NBINS+1];
__device__ int            g_ntiles;
__device__ int            g_pairnb[PAIR_CAP];          // neighbor point index per pair
__device__ int            g_slots[MAXN*MAXNB];         // per-point pair slots (fixed order)
__device__ unsigned char  g_pcnt[MAXN];
__device__ float          g_partial[PAIR_CAP*80];      // per-pair GEMV results (204.8 MB)

// ---------------- geometry tables (offsets with 1 <= d^2 <= 6 have nonzero K) ----------
__global__ void k_init()
{
    if (threadIdx.x == 0 && blockIdx.x == 0) {
        int bin = 0;
        for (int dx = -2; dx <= 2; dx++)
        for (int dy = -2; dy <= 2; dy++) {
            int row = (dx+2)*5 + (dy+2);
            int mask = 0;
            g_rowstart[row] = bin;
            for (int dz = -2; dz <= 2; dz++) {
                int d2 = dx*dx + dy*dy + dz*dz;
                if (d2 >= 1 && d2 <= 6) {
                    mask |= 1 << (dz+2);
                    g_bdx[bin] = dx; g_bdy[bin] = dy; g_bdz[bin] = dz;
                    bin++;
                }
            }
            g_rowmask[row] = mask;
        }
        // bin == 80 here by construction
    }
}

// clear ONLY the bitfield + counters (g_vol stale cells are unreachable)
__global__ void k_clear()
{
    int i = blockIdx.x*blockDim.x + threadIdx.x;
    if (i < BMW)   g_bm[i]  = 0u;
    if (i < NBINS) { g_counts[i] = 0; g_cursor[i] = 0; }
}

__global__ void k_scatter(const int* __restrict__ coords, int n)
{
    int i = blockIdx.x*blockDim.x + threadIdx.x;
    if (i >= n) return;
    int x = coords[3*i+0], y = coords[3*i+1], z = coords[3*i+2];
    g_vol[(x*GRIDN + y)*GRIDN + z] = i;
    atomicOr(&g_bm[(x*GRIDN + y)*6 + (z >> 5)], 1u << (z & 31));
}

// ---------------- build the 80 compacted 80x80 kernels from weight ----------------
__global__ void __launch_bounds__(256) k_buildK(const float* __restrict__ weight)
{
    int b = blockIdx.x, tid = threadIdx.x;
    int dx = g_bdx[b], dy = g_bdy[b], dz = g_bdz[b];
    float d2 = (float)(dx*dx + dy*dy + dz*dz);
    float d  = sqrtf(d2);
    float e[8];
    const float h = 2.5f / 9.0f;
    const float C = 1.14136f * expf(2.0f);
    #pragma unroll
    for (int r = 0; r < 8; r++) {
        float t  = (d - h*(float)(r+1)) / h;
        float tt = t*t;
        e[r] = (tt < 1.0f) ? C * expf(-2.0f / (1.0f - tt)) : 0.0f;
    }
    float inv = 1.7320508075688772f / d;   // sqrt(3)/|off|
    float vv[3] = { dx*inv, dy*inv, dz*inv };

    const float A  = 0.14433756729740643f;   // 1/sqrt(48)
    const float A3 = 1.0f / 12.0f;           // 1/(sqrt(48)*sqrt(3))

    for (int t = tid; t < 6400; t += 256) {
        int row = t / 80, col = t % 80;
        int wi = 0; float f = 0.0f; bool zero = false;
        if (row < 32 && col < 32) {            // K00 = A * w1[row][col]
            wi = row*32 + col; f = A;
        } else if (row < 32) {                 // K01[i][3k+m] = A * w2[i][k] * v[m]
            int ee = col - 32; int k = ee/3, m = ee - 3*k;
            wi = 1024 + row*16 + k; f = A * vv[m];
        } else if (col < 32) {                 // K10[3i+m][k] = A/sqrt3 * w4[i][k] * v[m]
            int ee = row - 32; int ii = ee/3, m = ee - 3*ii;
            wi = 1792 + ii*32 + col; f = A3 * vv[m];
        } else {                               // K11[3i+m][3k+n] = A * w3[i][k] * (m==n)
            int er = row - 32, ec = col - 32;
            int ii = er/3, m = er - 3*ii, k = ec/3, nn = ec - 3*k;
            if (m != nn) zero = true;
            wi = 1536 + ii*16 + k; f = A;
        }
        float val = 0.0f;
        if (!zero) {
            float w = 0.0f;
            #pragma unroll
            for (int r = 0; r < 8; r++) w += e[r] * __ldg(weight + r*2304 + wi);
            val = f * w * (1.0f / 125.0f);
        }
        g_K[b*6400 + t] = val;
    }
}

// ---------------- occupancy probe: 5 z-bits around z for column (xx,yy) ----------------
__device__ __forceinline__ unsigned occ5(int xx, int yy, int z)
{
    int base = (xx*GRIDN + yy)*6;
    int zl = z - 2;
    int q  = zl >> 5;                       // arithmetic shift: -1 for zl<0
    unsigned w0 = (q >= 0)   ? g_bm[base + q]     : 0u;
    unsigned w1 = (q + 1 < 6)? g_bm[base + q + 1] : 0u;
    unsigned v = __funnelshift_r(w0, w1, zl & 31) & 31u;
    if (zl + 4 > GRIDN - 1) v &= (31u >> (zl + 4 - (GRIDN - 1)));
    return v;
}

__global__ void k_count(const int* __restrict__ coords, int n)
{
    __shared__ int sb[NBINS];
    int tid = threadIdx.x;
    if (tid < NBINS) sb[tid] = 0;
    __syncthreads();
    int i = blockIdx.x*blockDim.x + tid;
    if (i < n) {
        int x = coords[3*i+0], y = coords[3*i+1], z = coords[3*i+2];
        int cnt = 0;
        #pragma unroll
        for (int row = 0; row < 25; row++) {
            int mask = g_rowmask[row];
            if (!mask) continue;
            int dx = row/5 - 2, dy = row%5 - 2;
            int xx = x + dx, yy = y + dy;
            if (xx < 0 || xx >= GRIDN || yy < 0 || yy >= GRIDN) continue;
            unsigned a = occ5(xx, yy, z) & (unsigned)mask;
            cnt += __popc(a);
            int rs = g_rowstart[row];
            while (a) {
                int bpos = __ffs(a) - 1; a &= a - 1;
                int bin = rs + __popc((unsigned)mask & ((1u << bpos) - 1u));
                atomicAdd(&sb[bin], 1);
            }
        }
        g_pcnt[i] = (unsigned char)min(cnt, 255);
    }
    __syncthreads();
    if (tid < NBINS) atomicAdd(&g_counts[tid], sb[tid]);
}

__global__ void k_scan()
{
    if (threadIdx.x == 0 && blockIdx.x == 0) {
        int acc = 0, tacc = 0;
        for (int b = 0; b < NBINS; b++) {
            g_binstart[b] = acc; g_tilestart[b] = tacc; g_cursor[b] = acc;
            int c = g_counts[b];
            acc += c; tacc += (c + TILE - 1) / TILE;
        }
        g_binstart[NBINS] = acc; g_tilestart[NBINS] = tacc; g_ntiles = tacc;
    }
}

__global__ void k_fill(const int* __restrict__ coords, int n)
{
    int i = blockIdx.x*blockDim.x + threadIdx.x;
    if (i >= n) return;
    int x = coords[3*i+0], y = coords[3*i+1], z = coords[3*i+2];
    int r = 0;
    #pragma unroll
    for (int row = 0; row < 25; row++) {
        int mask = g_rowmask[row];
        if (!mask) continue;
        int dx = row/5 - 2, dy = row%5 - 2;
        int xx = x + dx, yy = y + dy;
        if (xx < 0 || xx >= GRIDN || yy < 0 || yy >= GRIDN) continue;
        unsigned a = occ5(xx, yy, z) & (unsigned)mask;
        int rs = g_rowstart[row];
        while (a) {
            int bpos = __ffs(a) - 1; a &= a - 1;
            int bin = rs + __popc((unsigned)mask & ((1u << bpos) - 1u));
            int slot = atomicAdd(&g_cursor[bin], 1);
            if (slot < PAIR_CAP) {
                int zz = z - 2 + bpos;
                g_pairnb[slot] = g_vol[(xx*GRIDN + yy)*GRIDN + zz];
            }
            if (r < MAXNB) g_slots[i*MAXNB + r] = min(slot, PAIR_CAP - 1);
            r++;
        }
    }
}

// ---------------- binned GEMM: partial[s] = feats[nb(s)] @ K[bin(s)] ----------------
__global__ void __launch_bounds__(256) k_gemm(const float* __restrict__ feats)
{
    __shared__ float sF[TILE*80];
    __shared__ int   sPair[TILE];
    __shared__ int   sTS[NBINS+1], sBS[NBINS+1];
    int tid = threadIdx.x;
    if (tid < NBINS + 1) { sTS[tid] = g_tilestart[tid]; sBS[tid] = g_binstart[tid]; }
    __syncthreads();
    int ntiles = g_ntiles;
    int tx = tid & 15, ty = tid >> 4;      // 16 col-groups x 16 point-rows

    for (int t = blockIdx.x; t < ntiles; t += gridDim.x) {
        // locate bin via binary search on tile starts
        int lo = 0, hi = NBINS;
        while (hi - lo > 1) { int mid = (lo + hi) >> 1; if (sTS[mid] <= t) lo = mid; else hi = mid; }
        int b = lo;
        int pbase = sBS[b] + (t - sTS[b]) * TILE;
        int m = min(TILE, sBS[b+1] - pbase);

        if (tid < m) sPair[tid] = g_pairnb[pbase + tid];
        __syncthreads();

        { // gather feature rows (two threads per row, 40 floats each)
            int p = tid >> 1, half = tid & 1;
            float4* dst = (float4*)(sF + p*80 + half*40);
            if (p < m) {
                const float4* src = (const float4*)(feats + (long)sPair[p]*80 + half*40);
                #pragma unroll
                for (int q = 0; q < 10; q++) dst[q] = src[q];
            } else {
                float4 zz = make_float4(0.f, 0.f, 0.f, 0.f);
                #pragma unroll
                for (int q = 0; q < 10; q++) dst[q] = zz;
            }
        }
        __syncthreads();

        const float* Kb = g_K + b*6400;
        float acc[8][5];
        #pragma unroll
        for (int q = 0; q < 8; q++)
            #pragma unroll
            for (int j = 0; j < 5; j++) acc[q][j] = 0.0f;

        #pragma unroll 4
        for (int k = 0; k < 80; k++) {
            const float* kr = Kb + k*80 + tx*5;
            float w0 = __ldg(kr+0), w1 = __ldg(kr+1), w2 = __ldg(kr+2), w3 = __ldg(kr+3), w4 = __ldg(kr+4);
            #pragma unroll
            for (int q = 0; q < 8; q++) {
                float f = sF[(ty + 16*q)*80 + k];
                acc[q][0] += f*w0; acc[q][1] += f*w1; acc[q][2] += f*w2;
                acc[q][3] += f*w3; acc[q][4] += f*w4;
            }
        }

        float* Pb = g_partial + (long)pbase*80;
        #pragma unroll
        for (int q = 0; q < 8; q++) {
            int p = ty + 16*q;
            if (p < m) {
                float* o = Pb + p*80 + tx*5;
                o[0]=acc[q][0]; o[1]=acc[q][1]; o[2]=acc[q][2]; o[3]=acc[q][3]; o[4]=acc[q][4];
            }
        }
        __syncthreads();
    }
}

// ------------- finalize: out[i] = sc(feats[i]) + sum of partials (fixed order) -------------
__global__ void __launch_bounds__(256) k_final(const float* __restrict__ feats,
                                               const float* __restrict__ wsc0,
                                               const float* __restrict__ wsc1,
                                               float* __restrict__ out, int n)
{
    __shared__ float sW0[1024], sW1[256], sf[8][80];
    int tid = threadIdx.x;
    #pragma unroll
    for (int t = tid; t < 1024; t += 256) sW0[t] = wsc0[t] * 0.17677669529663687f; // /sqrt(32)
    sW1[tid] = wsc1[tid & 255] * 0.25f;                                            // /sqrt(16)
    __syncthreads();

    int w = tid >> 5, lane = tid & 31;
    int i = blockIdx.x*8 + w;
    if (i >= n) return;

    const float* fr = feats + (long)i*80;
    sf[w][lane]      = fr[lane];
    sf[w][lane + 32] = fr[lane + 32];
    if (lane < 16) sf[w][lane + 64] = fr[lane + 64];
    __syncwarp();

    float a0 = 0.f, a1 = 0.f, a2 = 0.f;
    #pragma unroll
    for (int ii = 0; ii < 32; ii++) a0 += sf[w][ii] * sW0[ii*32 + lane];
    {
        int k = lane / 3, m = lane - 3*k;            // col 32+lane  -> (k,m)
        #pragma unroll
        for (int ii = 0; ii < 16; ii++) a1 += sf[w][32 + 3*ii + m] * sW1[ii*16 + k];
    }
    if (lane < 16) {
        int e = lane + 32; int k = e / 3, m = e - 3*k; // col 64+lane -> (k,m)
        #pragma unroll
        for (int ii = 0; ii < 16; ii++) a2 += sf[w][32 + 3*ii + m] * sW1[ii*16 + k];
    }

    int cnt = min((int)g_pcnt[i], MAXNB);
    const int* sl = g_slots + i*MAXNB;
    for (int r = 0; r < cnt; r++) {
        const float* pp = g_partial + (long)sl[r]*80;
        a0 += pp[lane];
        a1 += pp[lane + 32];
        if (lane < 16) a2 += pp[lane + 64];
    }

    float* o = out + (long)i*80;
    o[lane] = a0; o[lane + 32] = a1;
    if (lane < 16) o[lane + 64] = a2;
}

// ------------------------------------ launch ------------------------------------
extern "C" void kernel_launch(void* const* d_in, const int* in_sizes, int n_in,
                              void* d_out, int out_size)
{
    const float* feats  = (const float*)d_in[0];
    const float* weight = (const float*)d_in[1];
    const float* w_sc0  = (const float*)d_in[2];
    const float* w_sc1  = (const float*)d_in[3];
    const int*   coords = (const int*)  d_in[4];
    int n = in_sizes[0] / 80;

    k_init   <<<1, 32>>>();
    k_clear  <<<(BMW + 255)/256, 256>>>();
    k_buildK <<<NBINS, 256>>>(weight);

    int nb = (n + 255) / 256;
    k_scatter<<<nb, 256>>>(coords, n);
    k_count  <<<nb, 256>>>(coords, n);
    k_scan   <<<1, 32>>>();
    k_fill   <<<nb, 256>>>(coords, n);

    k_gemm   <<<888, 256>>>(feats);
    k_final  <<<(n + 7)/8, 256>>>(feats, w_sc0, w_sc1, (float*)d_out, n);
}

// round 7
// speedup vs baseline: 1.3728x; 1.3728x over previous
#include <cuda_runtime.h>

#define GRIDN 192
#define VOLN (GRIDN*GRIDN*GRIDN)
#define BMW (GRIDN*GRIDN*6)
#define NBINS 80
#define MAXN 200000
#define MAXNB 32
#define BINCAP 8192
#define PAIR_CAP (NBINS*BINCAP)
#define TILE 128
#define FSTR 81   // padded smem feature stride (odd -> conflict-free)

// ---------------- persistent device scratch ----------------
// g_vol needs NO per-launch clear: only read at cells whose g_bm bit is set,
// and bits are only set at cells k_scatter wrote in THIS launch.
__device__ int            g_vol[VOLN];
__device__ unsigned       g_bm[BMW];
__device__ float          g_W[NBINS*2304];             // factorized per-bin weights (737 KB)
__device__ float          g_V[NBINS*4];                // vv = sqrt(3)*unit(offset)
__device__ int            g_rowmask[25];
__device__ int            g_rowstart[25];
__device__ int            g_bdx[NBINS], g_bdy[NBINS], g_bdz[NBINS];
__device__ int            g_cursor[NBINS];
__device__ int            g_tilestart[NBINS+1];
__device__ int            g_ntiles;
__device__ int            g_pairnb[PAIR_CAP];
__device__ int            g_slots[MAXN*MAXNB];
__device__ unsigned char  g_pcnt[MAXN];
__device__ float          g_partial[(size_t)PAIR_CAP*80];   // 210 MB

// ---------------- geometry tables (offsets with 1 <= d^2 <= 6 have nonzero K) ----------
__global__ void k_init()
{
    if (threadIdx.x == 0 && blockIdx.x == 0) {
        int bin = 0;
        for (int dx = -2; dx <= 2; dx++)
        for (int dy = -2; dy <= 2; dy++) {
            int row = (dx+2)*5 + (dy+2);
            int mask = 0;
            g_rowstart[row] = bin;
            for (int dz = -2; dz <= 2; dz++) {
                int d2 = dx*dx + dy*dy + dz*dz;
                if (d2 >= 1 && d2 <= 6) {
                    mask |= 1 << (dz+2);
                    g_bdx[bin] = dx; g_bdy[bin] = dy; g_bdz[bin] = dz;
                    float inv = 1.7320508075688772f / sqrtf((float)d2);
                    g_V[bin*4+0] = dx*inv; g_V[bin*4+1] = dy*inv; g_V[bin*4+2] = dz*inv;
                    bin++;
                }
            }
            g_rowmask[row] = mask;
        }
    }
}

__global__ void k_clear()
{
    int i = blockIdx.x*blockDim.x + threadIdx.x;
    if (i < BMW)   g_bm[i]  = 0u;
    if (i < NBINS) g_cursor[i] = 0;
}

__global__ void k_scatter(const int* __restrict__ coords, int n)
{
    int i = blockIdx.x*blockDim.x + threadIdx.x;
    if (i >= n) return;
    int x = coords[3*i+0], y = coords[3*i+1], z = coords[3*i+2];
    g_vol[(x*GRIDN + y)*GRIDN + z] = i;
    atomicOr(&g_bm[(x*GRIDN + y)*6 + (z >> 5)], 1u << (z & 31));
}

// ---------------- factorized per-bin weights: g_W[b] = scale * (EMB[b] @ weight)/125 ----
// layout matches weight rows: [0,1024) w1(32x32)*A, [1024,1536) w2(32x16)*A,
// [1536,1792) w3(16x16)*A, [1792,2304) w4(16x32)*A/sqrt(3)
__global__ void __launch_bounds__(256) k_buildW(const float* __restrict__ weight)
{
    int b = blockIdx.x, tid = threadIdx.x;
    int dx = g_bdx[b], dy = g_bdy[b], dz = g_bdz[b];
    float d = sqrtf((float)(dx*dx + dy*dy + dz*dz));
    float e[8];
    const float h = 2.5f / 9.0f;
    const float C = 1.14136f * expf(2.0f);
    #pragma unroll
    for (int r = 0; r < 8; r++) {
        float t  = (d - h*(float)(r+1)) / h;
        float tt = t*t;
        e[r] = (tt < 1.0f) ? C * expf(-2.0f / (1.0f - tt)) : 0.0f;
    }
    const float A  = 0.14433756729740643f;   // 1/sqrt(48)
    const float A3 = 1.0f / 12.0f;           // A/sqrt(3)
    for (int j = tid; j < 2304; j += 256) {
        float w = 0.0f;
        #pragma unroll
        for (int r = 0; r < 8; r++) w += e[r] * __ldg(weight + r*2304 + j);
        float s = (j >= 1792) ? A3 : A;
        g_W[b*2304 + j] = s * w * (1.0f / 125.0f);
    }
}

// ---------------- occupancy probe: 5 z-bits around z for column (xx,yy) ----------------
__device__ __forceinline__ unsigned occ5(int xx, int yy, int z)
{
    int base = (xx*GRIDN + yy)*6;
    int zl = z - 2;
    int q  = zl >> 5;
    unsigned w0 = (q >= 0)   ? g_bm[base + q]     : 0u;
    unsigned w1 = (q + 1 < 6)? g_bm[base + q + 1] : 0u;
    unsigned v = __funnelshift_r(w0, w1, zl & 31) & 31u;
    if (zl + 4 > GRIDN - 1) v &= (31u >> (zl + 4 - (GRIDN - 1)));
    return v;
}

// single discovery pass: claim slots directly in fixed-capacity bins
__global__ void k_fill(const int* __restrict__ coords, int n)
{
    int i = blockIdx.x*blockDim.x + threadIdx.x;
    if (i >= n) return;
    int x = coords[3*i+0], y = coords[3*i+1], z = coords[3*i+2];
    int r = 0;
    #pragma unroll
    for (int row = 0; row < 25; row++) {
        int mask = g_rowmask[row];
        if (!mask) continue;
        int dx = row/5 - 2, dy = row%5 - 2;
        int xx = x + dx, yy = y + dy;
        if (xx < 0 || xx >= GRIDN || yy < 0 || yy >= GRIDN) continue;
        unsigned a = occ5(xx, yy, z) & (unsigned)mask;
        int rs = g_rowstart[row];
        while (a) {
            int bpos = __ffs(a) - 1; a &= a - 1;
            int bin = rs + __popc((unsigned)mask & ((1u << bpos) - 1u));
            int loc = atomicAdd(&g_cursor[bin], 1);
            if (loc < BINCAP) {
                int slot = bin*BINCAP + loc;
                int zz = z - 2 + bpos;
                g_pairnb[slot] = g_vol[(xx*GRIDN + yy)*GRIDN + zz];
                if (r < MAXNB) { g_slots[i*MAXNB + r] = slot; r++; }
            }
        }
    }
    g_pcnt[i] = (unsigned char)r;
}

__global__ void k_scan()
{
    if (threadIdx.x == 0 && blockIdx.x == 0) {
        int tacc = 0;
        for (int b = 0; b < NBINS; b++) {
            g_tilestart[b] = tacc;
            int c = min(g_cursor[b], BINCAP);
            tacc += (c + TILE - 1) / TILE;
        }
        g_tilestart[NBINS] = tacc; g_ntiles = tacc;
    }
}

// ---------------- factorized binned GEMM: partial[slot] = feats[nb] @ K[bin] ----------
// out0[c]     = sum_i f0[i]*W1[i][c] + sum_i f1v[i]*W4[i][c]
// h[k]        = sum_i f0[i]*W2[i][k]
// out1[3k+n]  = vv[n]*h[k] + sum_i f1[3i+n]*W3[i][k]
__global__ void __launch_bounds__(128) k_gemm(const float* __restrict__ feats)
{
    __shared__ float sF[TILE*FSTR];
    __shared__ float sW[2304];
    __shared__ float sVV[4];
    __shared__ int   sPair[TILE];
    __shared__ int   sTS[NBINS+1];
    __shared__ int   sCnt[NBINS];
    int tid = threadIdx.x;
    if (tid < NBINS + 1) sTS[tid] = g_tilestart[tid];
    if (tid < NBINS)     sCnt[tid] = min(g_cursor[tid], BINCAP);
    __syncthreads();
    int ntiles = g_ntiles;

    for (int t = blockIdx.x; t < ntiles; t += gridDim.x) {
        int lo = 0, hi = NBINS;
        while (hi - lo > 1) { int mid = (lo + hi) >> 1; if (sTS[mid] <= t) lo = mid; else hi = mid; }
        int b = lo;
        int tloc  = t - sTS[b];
        int pbase = b*BINCAP + tloc*TILE;
        int m = min(TILE, sCnt[b] - tloc*TILE);

        if (tid < m) sPair[tid] = g_pairnb[pbase + tid];
        // bin weights -> smem (coalesced)
        #pragma unroll
        for (int q = 0; q < 18; q++) sW[q*128 + tid] = g_W[b*2304 + q*128 + tid];
        if (tid < 3) sVV[tid] = g_V[b*4 + tid];
        __syncthreads();

        { // stage feature rows: 2 threads per row, scalar STS into padded stride
            #pragma unroll
            for (int pass = 0; pass < 2; pass++) {
                int p = pass*64 + (tid >> 1), half = tid & 1;
                if (p < m) {
                    const float4* src = (const float4*)(feats + (size_t)sPair[p]*80 + half*40);
                    float* dst = sF + p*FSTR + half*40;
                    #pragma unroll
                    for (int q = 0; q < 10; q++) {
                        float4 v = src[q];
                        dst[q*4+0]=v.x; dst[q*4+1]=v.y; dst[q*4+2]=v.z; dst[q*4+3]=v.w;
                    }
                }
            }
        }
        __syncthreads();

        int p = tid;
        if (p < m) {
            const float* f = sF + p*FSTR;
            float vv0 = sVV[0], vv1 = sVV[1], vv2 = sVV[2];

            // f1v[i] = sum_m f1[3i+m]*vv[m]
            float f1v[16];
            #pragma unroll
            for (int i = 0; i < 16; i++)
                f1v[i] = f[32+3*i]*vv0 + f[33+3*i]*vv1 + f[34+3*i]*vv2;

            float a0[32], hh[16];
            #pragma unroll
            for (int c = 0; c < 32; c++) a0[c] = 0.0f;
            #pragma unroll
            for (int k = 0; k < 16; k++) hh[k] = 0.0f;

            #pragma unroll 4
            for (int i = 0; i < 32; i++) {
                float fi = f[i];
                const float* w1r = sW + i*32;
                #pragma unroll
                for (int c = 0; c < 32; c++) a0[c] += fi * w1r[c];
                const float* w2r = sW + 1024 + i*16;
                #pragma unroll
                for (int k = 0; k < 16; k++) hh[k] += fi * w2r[k];
            }
            #pragma unroll 4
            for (int i = 0; i < 16; i++) {
                float fi = f1v[i];
                const float* w4r = sW + 1792 + i*32;
                #pragma unroll
                for (int c = 0; c < 32; c++) a0[c] += fi * w4r[c];
            }

            float* orow = g_partial + (size_t)(pbase + p)*80;
            #pragma unroll
            for (int q = 0; q < 8; q++)
                ((float4*)orow)[q] = make_float4(a0[q*4], a0[q*4+1], a0[q*4+2], a0[q*4+3]);

            float o1[48];
            #pragma unroll
            for (int k = 0; k < 16; k++) {
                o1[3*k]   = vv0 * hh[k];
                o1[3*k+1] = vv1 * hh[k];
                o1[3*k+2] = vv2 * hh[k];
            }
            #pragma unroll 2
            for (int i = 0; i < 16; i++) {
                float fa = f[32+3*i], fb = f[33+3*i], fc = f[34+3*i];
                const float* w3r = sW + 1536 + i*16;
                #pragma unroll
                for (int k = 0; k < 16; k++) {
                    float w = w3r[k];
                    o1[3*k]   += fa * w;
                    o1[3*k+1] += fb * w;
                    o1[3*k+2] += fc * w;
                }
            }
            #pragma unroll
            for (int q = 0; q < 12; q++)
                ((float4*)(orow+32))[q] = make_float4(o1[q*4], o1[q*4+1], o1[q*4+2], o1[q*4+3]);
        }
        __syncthreads();
    }
}

// ------------- finalize: out[i] = sc(feats[i]) + sum of partials (fixed order) -------------
__global__ void __launch_bounds__(256) k_final(const float* __restrict__ feats,
                                               const float* __restrict__ wsc0,
                                               const float* __restrict__ wsc1,
                                               float* __restrict__ out, int n)
{
    __shared__ float sW0[1024], sW1[256], sf[8][80];
    int tid = threadIdx.x;
    #pragma unroll
    for (int t = tid; t < 1024; t += 256) sW0[t] = wsc0[t] * 0.17677669529663687f; // /sqrt(32)
    sW1[tid] = wsc1[tid & 255] * 0.25f;                                            // /sqrt(16)
    __syncthreads();

    int w = tid >> 5, lane = tid & 31;
    int i = blockIdx.x*8 + w;
    if (i >= n) return;

    const float* fr = feats + (size_t)i*80;
    sf[w][lane]      = fr[lane];
    sf[w][lane + 32] = fr[lane + 32];
    if (lane < 16) sf[w][lane + 64] = fr[lane + 64];
    __syncwarp();

    float a0 = 0.f, a1 = 0.f, a2 = 0.f;
    #pragma unroll
    for (int ii = 0; ii < 32; ii++) a0 += sf[w][ii] * sW0[ii*32 + lane];
    {
        int k = lane / 3, m = lane - 3*k;
        #pragma unroll
        for (int ii = 0; ii < 16; ii++) a1 += sf[w][32 + 3*ii + m] * sW1[ii*16 + k];
    }
    if (lane < 16) {
        int e = lane + 32; int k = e / 3, m = e - 3*k;
        #pragma unroll
        for (int ii = 0; ii < 16; ii++) a2 += sf[w][32 + 3*ii + m] * sW1[ii*16 + k];
    }

    int cnt = (int)g_pcnt[i];
    const int* sl = g_slots + i*MAXNB;
    for (int r = 0; r < cnt; r++) {
        const float* pp = g_partial + (size_t)sl[r]*80;
        a0 += pp[lane];
        a1 += pp[lane + 32];
        if (lane < 16) a2 += pp[lane + 64];
    }

    float* o = out + (size_t)i*80;
    o[lane] = a0; o[lane + 32] = a1;
    if (lane < 16) o[lane + 64] = a2;
}

// ------------------------------------ launch ------------------------------------
extern "C" void kernel_launch(void* const* d_in, const int* in_sizes, int n_in,
                              void* d_out, int out_size)
{
    const float* feats  = (const float*)d_in[0];
    const float* weight = (const float*)d_in[1];
    const float* w_sc0  = (const float*)d_in[2];
    const float* w_sc1  = (const float*)d_in[3];
    const int*   coords = (const int*)  d_in[4];
    int n = in_sizes[0] / 80;

    k_init   <<<1, 32>>>();
    k_clear  <<<(BMW + 255)/256, 256>>>();
    k_buildW <<<NBINS, 256>>>(weight);

    int nb = (n + 255) / 256;
    k_scatter<<<nb, 256>>>(coords, n);
    k_fill   <<<nb, 256>>>(coords, n);
    k_scan   <<<1, 32>>>();

    k_gemm   <<<592, 128>>>(feats);
    k_final  <<<(n + 7)/8, 256>>>(feats, w_sc0, w_sc1, (float*)d_out, n);
}